// round 10
// baseline (speedup 1.0000x reference)
#include <cuda_runtime.h>
#include <cuda_bf16.h>
#include <math.h>
#include <stdint.h>

#define NN 50000
#define NE 800000
#define CD 128
#define AH 64

// ---------------- scratch (static device globals) ---------------------------------
__device__ float g_nsq[NN];
__device__ float g_ns[NN];
__device__ float g_n3sq[NN];
__device__ float g_n4sq[NN];
__device__ float g_s4[NN];
__device__ int   g_degcur[2 * NN];   // [0..NN) deg, [NN..2NN) cursor
__device__ int   g_rowptr[NN + 1];
__device__ int   g_csr[NE];
__device__ float g_w[(size_t)NN * 4];    // attention logits [node][branch]
// split-bf16 feature matrices (hi/lo)
__device__ __nv_bfloat16 g_xh[(size_t)NN * CD];
__device__ __nv_bfloat16 g_xl[(size_t)NN * CD];
__device__ __nv_bfloat16 g_agch[(size_t)NN * CD];
__device__ __nv_bfloat16 g_agcl[(size_t)NN * CD];
__device__ __nv_bfloat16 g_ageh[(size_t)NN * CD];
__device__ __nv_bfloat16 g_agel[(size_t)NN * CD];
__device__ __nv_bfloat16 g_x3h[(size_t)NN * CD];
__device__ __nv_bfloat16 g_x3l[(size_t)NN * CD];
__device__ __nv_bfloat16 g_x4h[(size_t)NN * CD];
__device__ __nv_bfloat16 g_x4l[(size_t)NN * CD];
__device__ __nv_bfloat16 g_x1h[(size_t)NN * CD];
__device__ __nv_bfloat16 g_x1l[(size_t)NN * CD];
__device__ __nv_bfloat16 g_x2h[(size_t)NN * CD];
__device__ __nv_bfloat16 g_x2l[(size_t)NN * CD];
// split-bf16 transposed weights: [N rows x K cols]
__device__ __nv_bfloat16 g_w0h[128 * 256];
__device__ __nv_bfloat16 g_w0l[128 * 256];
__device__ __nv_bfloat16 g_w1h[128 * 256];
__device__ __nv_bfloat16 g_w1l[128 * 256];
__device__ __nv_bfloat16 g_wah[64 * 128];
__device__ __nv_bfloat16 g_wal[64 * 128];

struct GemmPtrs {
    const __nv_bfloat16* A1h[4];
    const __nv_bfloat16* A1l[4];
    const __nv_bfloat16* A2h[4];
    const __nv_bfloat16* A2l[4];
    float*               C[4];    // fp32 out (layer1)
    __nv_bfloat16*       Ch[4];   // split out hi
    __nv_bfloat16*       Cl[4];   // split out lo
};

__device__ __forceinline__ uint32_t smem_u32(const void* p) {
    uint32_t a;
    asm("{ .reg .u64 t; cvta.to.shared.u64 t, %1; cvt.u32.u64 %0, t; }" : "=r"(a) : "l"(p));
    return a;
}

__device__ __forceinline__ float wredsum(float v) {
#pragma unroll
    for (int o = 16; o; o >>= 1) v += __shfl_xor_sync(0xffffffffu, v, o);
    return v;
}

__device__ __forceinline__ uint32_t pack_bf16(float a, float b) {
    __nv_bfloat16 h0 = __float2bfloat16(a);
    __nv_bfloat16 h1 = __float2bfloat16(b);
    return (uint32_t)__bfloat16_as_ushort(h0) | ((uint32_t)__bfloat16_as_ushort(h1) << 16);
}
// split two floats into packed hi / packed lo words
__device__ __forceinline__ void split2(float a, float b, uint32_t& hw, uint32_t& lw) {
    __nv_bfloat16 h0 = __float2bfloat16(a);
    __nv_bfloat16 h1 = __float2bfloat16(b);
    hw = (uint32_t)__bfloat16_as_ushort(h0) | ((uint32_t)__bfloat16_as_ushort(h1) << 16);
    float ra = a - __bfloat162float(h0);
    float rb = b - __bfloat162float(h1);
    lw = pack_bf16(ra, rb);
}

// ---------------- per-node stats of x + x split + zero degcur ----------------------
__global__ void k_stats1(const float* __restrict__ x) {
    int gid = blockIdx.x * 256 + threadIdx.x;
    if (gid < 2 * NN) g_degcur[gid] = 0;
    int node = blockIdx.x * 8 + (threadIdx.x >> 5);
    if (node >= NN) return;
    int lane = threadIdx.x & 31;
    float4 v = *(const float4*)(x + (size_t)node * CD + lane * 4);
    uint32_t h0, l0, h1, l1;
    split2(v.x, v.y, h0, l0);
    split2(v.z, v.w, h1, l1);
    size_t off = (size_t)node * CD + lane * 4;
    *(uint2*)(g_xh + off) = make_uint2(h0, h1);
    *(uint2*)(g_xl + off) = make_uint2(l0, l1);
    float sq = v.x * v.x + v.y * v.y + v.z * v.z + v.w * v.w;
    float s  = v.x + v.y + v.z + v.w;
    sq = wredsum(sq);
    s  = wredsum(s);
    if (lane == 0) { g_nsq[node] = sq; g_ns[node] = s; }
}

// ---------------- CSR build -------------------------------------------------------
__global__ void k_deg(const int* __restrict__ row) {
    int e = blockIdx.x * blockDim.x + threadIdx.x;
    if (e < NE) atomicAdd(&g_degcur[row[e]], 1);
}

__global__ void k_scan() {
    const int PER = (NN + 1023) / 1024;
    int tid = threadIdx.x;
    int t0 = tid * PER;
    int sum = 0;
    for (int i = 0; i < PER; i++) {
        int idx = t0 + i;
        if (idx < NN) sum += g_degcur[idx];
    }
    int lane = tid & 31, wid = tid >> 5;
    int v = sum;
#pragma unroll
    for (int o = 1; o < 32; o <<= 1) {
        int t = __shfl_up_sync(0xffffffffu, v, o);
        if (lane >= o) v += t;
    }
    __shared__ int wsum[32];
    if (lane == 31) wsum[wid] = v;
    __syncthreads();
    if (wid == 0) {
        int w = wsum[lane];
#pragma unroll
        for (int o = 1; o < 32; o <<= 1) {
            int t = __shfl_up_sync(0xffffffffu, w, o);
            if (lane >= o) w += t;
        }
        wsum[lane] = w;
    }
    __syncthreads();
    int offset = v - sum + (wid ? wsum[wid - 1] : 0);
    int run = offset;
    for (int i = 0; i < PER; i++) {
        int idx = t0 + i;
        if (idx < NN) { g_rowptr[idx] = run; run += g_degcur[idx]; }
    }
    if (t0 < NN && t0 + PER >= NN) g_rowptr[NN] = run;
}

__global__ void k_scatter(const int* __restrict__ row, const int* __restrict__ col) {
    int e = blockIdx.x * blockDim.x + threadIdx.x;
    if (e >= NE) return;
    int r = row[e];
    int p = atomicAdd(&g_degcur[NN + r], 1);
    g_csr[g_rowptr[r] + p] = col[e];
}

// ---------------- fused weight prep: transpose + bf16 split ------------------------
__global__ void k_prep_all(const float* __restrict__ Wl0, const float* __restrict__ Wr0,
                           const float* __restrict__ Wl1, const float* __restrict__ Wr1,
                           const float* __restrict__ attW1) {
    int i = blockIdx.x * blockDim.x + threadIdx.x;
    float v;
    __nv_bfloat16 *oh, *ol;
    int idx;
    if (i < 32768) {
        int n = i / 256, k = i % 256;
        v = (k < 128) ? Wl0[(size_t)k * 128 + n] : Wr0[(size_t)(k - 128) * 128 + n];
        oh = g_w0h; ol = g_w0l; idx = i;
    } else if (i < 65536) {
        int j = i - 32768;
        int n = j / 256, k = j % 256;
        v = (k < 128) ? Wl1[(size_t)k * 128 + n] : Wr1[(size_t)(k - 128) * 128 + n];
        oh = g_w1h; ol = g_w1l; idx = j;
    } else if (i < 73728) {
        int j = i - 65536;
        int n = j / 128, k = j % 128;
        v = attW1[(size_t)k * 64 + n];
        oh = g_wah; ol = g_wal; idx = j;
    } else return;
    __nv_bfloat16 h = __float2bfloat16(v);
    oh[idx] = h;
    ol[idx] = __float2bfloat16(v - __bfloat162float(h));
}

// ---------------- fused layer-1 agg: warp/node, half-warp/edge, unroll 2 -----------
__global__ void k_agg1(const float* __restrict__ x) {
    int node = blockIdx.x * 8 + (threadIdx.x >> 5);
    if (node >= NN) return;
    int lane = threadIdx.x & 31;
    int half = lane >> 4, sub = lane & 15;
    const float4* xb = (const float4*)x;
    float4 xi0 = xb[(size_t)node * 32 + sub * 2];
    float4 xi1 = xb[(size_t)node * 32 + sub * 2 + 1];
    float nsq_i = g_nsq[node], ns_i = g_ns[node];
    int s = g_rowptr[node], t = g_rowptr[node + 1];
    float ac[8] = {0.f, 0.f, 0.f, 0.f, 0.f, 0.f, 0.f, 0.f};
    float ae[8] = {0.f, 0.f, 0.f, 0.f, 0.f, 0.f, 0.f, 0.f};
    for (int base = s; base < t; base += 4) {
        int jA = base + half, jB = base + 2 + half;
        bool okA = jA < t, okB = jB < t;
        int cA = okA ? __ldg(&g_csr[jA]) : node;
        int cB = okB ? __ldg(&g_csr[jB]) : node;
        float4 vA0 = xb[(size_t)cA * 32 + sub * 2];
        float4 vA1 = xb[(size_t)cA * 32 + sub * 2 + 1];
        float4 vB0 = xb[(size_t)cB * 32 + sub * 2];
        float4 vB1 = xb[(size_t)cB * 32 + sub * 2 + 1];
        float dA = xi0.x * vA0.x + xi0.y * vA0.y + xi0.z * vA0.z + xi0.w * vA0.w
                 + xi1.x * vA1.x + xi1.y * vA1.y + xi1.z * vA1.z + xi1.w * vA1.w;
        float dB = xi0.x * vB0.x + xi0.y * vB0.y + xi0.z * vB0.z + xi0.w * vB0.w
                 + xi1.x * vB1.x + xi1.y * vB1.y + xi1.z * vB1.z + xi1.w * vB1.w;
#pragma unroll
        for (int o = 8; o; o >>= 1) {
            dA += __shfl_xor_sync(0xffffffffu, dA, o);
            dB += __shfl_xor_sync(0xffffffffu, dB, o);
        }
        float nsqA = g_nsq[cA], nsA = g_ns[cA];
        float nsqB = g_nsq[cB], nsB = g_ns[cB];
        float wcA = dA / fmaxf(sqrtf(nsq_i * nsqA), 1e-8f);
        float qA = nsq_i + nsqA - 2.f * dA + 2e-6f * (ns_i - nsA) + 1.28e-10f;
        float weA = sqrtf(fmaxf(qA, 0.f));
        float wcB = dB / fmaxf(sqrtf(nsq_i * nsqB), 1e-8f);
        float qB = nsq_i + nsqB - 2.f * dB + 2e-6f * (ns_i - nsB) + 1.28e-10f;
        float weB = sqrtf(fmaxf(qB, 0.f));
        if (!okA) { wcA = 0.f; weA = 0.f; }
        if (!okB) { wcB = 0.f; weB = 0.f; }
        ac[0] += wcA * vA0.x + wcB * vB0.x; ac[1] += wcA * vA0.y + wcB * vB0.y;
        ac[2] += wcA * vA0.z + wcB * vB0.z; ac[3] += wcA * vA0.w + wcB * vB0.w;
        ac[4] += wcA * vA1.x + wcB * vB1.x; ac[5] += wcA * vA1.y + wcB * vB1.y;
        ac[6] += wcA * vA1.z + wcB * vB1.z; ac[7] += wcA * vA1.w + wcB * vB1.w;
        ae[0] += weA * vA0.x + weB * vB0.x; ae[1] += weA * vA0.y + weB * vB0.y;
        ae[2] += weA * vA0.z + weB * vB0.z; ae[3] += weA * vA0.w + weB * vB0.w;
        ae[4] += weA * vA1.x + weB * vB1.x; ae[5] += weA * vA1.y + weB * vB1.y;
        ae[6] += weA * vA1.z + weB * vB1.z; ae[7] += weA * vA1.w + weB * vB1.w;
    }
#pragma unroll
    for (int i = 0; i < 8; i++) {
        ac[i] += __shfl_xor_sync(0xffffffffu, ac[i], 16);
        ae[i] += __shfl_xor_sync(0xffffffffu, ae[i], 16);
    }
    float inv = 1.f / (float)max(t - s, 1);
    int b = half * 4;
    size_t off = (size_t)node * CD + (sub * 2 + half) * 4;
    uint32_t h0, l0, h1, l1;
    split2(ac[b] * inv, ac[b + 1] * inv, h0, l0);
    split2(ac[b + 2] * inv, ac[b + 3] * inv, h1, l1);
    *(uint2*)(g_agch + off) = make_uint2(h0, h1);
    *(uint2*)(g_agcl + off) = make_uint2(l0, l1);
    split2(ae[b] * inv, ae[b + 1] * inv, h0, l0);
    split2(ae[b + 2] * inv, ae[b + 3] * inv, h1, l1);
    *(uint2*)(g_ageh + off) = make_uint2(h0, h1);
    *(uint2*)(g_agel + off) = make_uint2(l0, l1);
}

// ---------------- fused layer-2 agg: warp/node, half-warp/edge, unroll 2 -----------
__global__ void k_agg2(const float* __restrict__ x3, const float* __restrict__ x4) {
    int node = blockIdx.x * 8 + (threadIdx.x >> 5);
    if (node >= NN) return;
    int lane = threadIdx.x & 31;
    int half = lane >> 4, sub = lane & 15;
    const float4* x3b = (const float4*)x3;
    const float4* x4b = (const float4*)x4;
    float4 a30 = x3b[(size_t)node * 32 + sub * 2];
    float4 a31 = x3b[(size_t)node * 32 + sub * 2 + 1];
    float4 a40 = x4b[(size_t)node * 32 + sub * 2];
    float4 a41 = x4b[(size_t)node * 32 + sub * 2 + 1];
    float n3i = g_n3sq[node], n4i = g_n4sq[node], s4i = g_s4[node];
    int s = g_rowptr[node], t = g_rowptr[node + 1];
    float ac[8] = {0.f, 0.f, 0.f, 0.f, 0.f, 0.f, 0.f, 0.f};
    float ae[8] = {0.f, 0.f, 0.f, 0.f, 0.f, 0.f, 0.f, 0.f};
    for (int base = s; base < t; base += 4) {
        int jA = base + half, jB = base + 2 + half;
        bool okA = jA < t, okB = jB < t;
        int cA = okA ? __ldg(&g_csr[jA]) : node;
        int cB = okB ? __ldg(&g_csr[jB]) : node;
        float4 vA30 = x3b[(size_t)cA * 32 + sub * 2];
        float4 vA31 = x3b[(size_t)cA * 32 + sub * 2 + 1];
        float4 vA40 = x4b[(size_t)cA * 32 + sub * 2];
        float4 vA41 = x4b[(size_t)cA * 32 + sub * 2 + 1];
        float4 vB30 = x3b[(size_t)cB * 32 + sub * 2];
        float4 vB31 = x3b[(size_t)cB * 32 + sub * 2 + 1];
        float4 vB40 = x4b[(size_t)cB * 32 + sub * 2];
        float4 vB41 = x4b[(size_t)cB * 32 + sub * 2 + 1];
        float d3A = a30.x * vA30.x + a30.y * vA30.y + a30.z * vA30.z + a30.w * vA30.w
                  + a31.x * vA31.x + a31.y * vA31.y + a31.z * vA31.z + a31.w * vA31.w;
        float d4A = a40.x * vA40.x + a40.y * vA40.y + a40.z * vA40.z + a40.w * vA40.w
                  + a41.x * vA41.x + a41.y * vA41.y + a41.z * vA41.z + a41.w * vA41.w;
        float d3B = a30.x * vB30.x + a30.y * vB30.y + a30.z * vB30.z + a30.w * vB30.w
                  + a31.x * vB31.x + a31.y * vB31.y + a31.z * vB31.z + a31.w * vB31.w;
        float d4B = a40.x * vB40.x + a40.y * vB40.y + a40.z * vB40.z + a40.w * vB40.w
                  + a41.x * vB41.x + a41.y * vB41.y + a41.z * vB41.z + a41.w * vB41.w;
#pragma unroll
        for (int o = 8; o; o >>= 1) {
            d3A += __shfl_xor_sync(0xffffffffu, d3A, o);
            d4A += __shfl_xor_sync(0xffffffffu, d4A, o);
            d3B += __shfl_xor_sync(0xffffffffu, d3B, o);
            d4B += __shfl_xor_sync(0xffffffffu, d4B, o);
        }
        float wcA = d3A / fmaxf(sqrtf(n3i * g_n3sq[cA]), 1e-8f);
        float qA = n4i + g_n4sq[cA] - 2.f * d4A + 2e-6f * (s4i - g_s4[cA]) + 1.28e-10f;
        float weA = sqrtf(fmaxf(qA, 0.f));
        float wcB = d3B / fmaxf(sqrtf(n3i * g_n3sq[cB]), 1e-8f);
        float qB = n4i + g_n4sq[cB] - 2.f * d4B + 2e-6f * (s4i - g_s4[cB]) + 1.28e-10f;
        float weB = sqrtf(fmaxf(qB, 0.f));
        if (!okA) { wcA = 0.f; weA = 0.f; }
        if (!okB) { wcB = 0.f; weB = 0.f; }
        ac[0] += wcA * vA30.x + wcB * vB30.x; ac[1] += wcA * vA30.y + wcB * vB30.y;
        ac[2] += wcA * vA30.z + wcB * vB30.z; ac[3] += wcA * vA30.w + wcB * vB30.w;
        ac[4] += wcA * vA31.x + wcB * vB31.x; ac[5] += wcA * vA31.y + wcB * vB31.y;
        ac[6] += wcA * vA31.z + wcB * vB31.z; ac[7] += wcA * vA31.w + wcB * vB31.w;
        ae[0] += weA * vA40.x + weB * vB40.x; ae[1] += weA * vA40.y + weB * vB40.y;
        ae[2] += weA * vA40.z + weB * vB40.z; ae[3] += weA * vA40.w + weB * vB40.w;
        ae[4] += weA * vA41.x + weB * vB41.x; ae[5] += weA * vA41.y + weB * vB41.y;
        ae[6] += weA * vA41.z + weB * vB41.z; ae[7] += weA * vA41.w + weB * vB41.w;
    }
#pragma unroll
    for (int i = 0; i < 8; i++) {
        ac[i] += __shfl_xor_sync(0xffffffffu, ac[i], 16);
        ae[i] += __shfl_xor_sync(0xffffffffu, ae[i], 16);
    }
    float inv = 1.f / (float)max(t - s, 1);
    int b = half * 4;
    size_t off = (size_t)node * CD + (sub * 2 + half) * 4;
    uint32_t h0, l0, h1, l1;
    split2(ac[b] * inv, ac[b + 1] * inv, h0, l0);
    split2(ac[b + 2] * inv, ac[b + 3] * inv, h1, l1);
    *(uint2*)(g_agch + off) = make_uint2(h0, h1);
    *(uint2*)(g_agcl + off) = make_uint2(l0, l1);
    split2(ae[b] * inv, ae[b + 1] * inv, h0, l0);
    split2(ae[b + 2] * inv, ae[b + 3] * inv, h1, l1);
    *(uint2*)(g_ageh + off) = make_uint2(h0, h1);
    *(uint2*)(g_agel + off) = make_uint2(l0, l1);
}

// ---------------- mma helpers ------------------------------------------------------
__device__ __forceinline__ void ldm_x4(uint32_t* r, uint32_t addr) {
    asm volatile("ldmatrix.sync.aligned.m8n8.x4.shared.b16 {%0,%1,%2,%3}, [%4];"
                 : "=r"(r[0]), "=r"(r[1]), "=r"(r[2]), "=r"(r[3]) : "r"(addr));
}
__device__ __forceinline__ void mma_bf16(float* c, const uint32_t* a, const uint32_t* b) {
    asm volatile(
        "mma.sync.aligned.m16n8k16.row.col.f32.bf16.bf16.f32 "
        "{%0,%1,%2,%3}, {%4,%5,%6,%7}, {%8,%9}, {%0,%1,%2,%3};"
        : "+f"(c[0]), "+f"(c[1]), "+f"(c[2]), "+f"(c[3])
        : "r"(a[0]), "r"(a[1]), "r"(a[2]), "r"(a[3]), "r"(b[0]), "r"(b[1]));
}

// ---------------- split-bf16 tensor-core GEMM (batched via blockIdx.y) -------------
// MODE: 0 = layer2 (write split only), 1 = layer1 (relu + fp32 + split + row stats),
//       3 = attention (tanh + dot attW2 -> wout[node][y])
template <int BN, int KT, int MODE>
__global__ __launch_bounds__(256, 2) void k_mma_gemm(
    GemmPtrs ptrs,
    const __nv_bfloat16* __restrict__ Bhg, const __nv_bfloat16* __restrict__ Blg,
    const float* __restrict__ bias, const float* __restrict__ W2,
    float* __restrict__ wout, int M) {
    constexpr int BK = 32;
    constexpr int PITCH = 40;
    constexpr int NT = BN / 16;

    __shared__ __nv_bfloat16 sAh[128 * PITCH];
    __shared__ __nv_bfloat16 sAl[128 * PITCH];
    __shared__ __nv_bfloat16 sBh[BN * PITCH];
    __shared__ __nv_bfloat16 sBl[BN * PITCH];
    __shared__ float s_r0[2][128];
    __shared__ float s_r1[2][128];

    int y = blockIdx.y;
    const __nv_bfloat16* A1h = ptrs.A1h[y];
    const __nv_bfloat16* A1l = ptrs.A1l[y];
    const __nv_bfloat16* A2h = ptrs.A2h[y];
    const __nv_bfloat16* A2l = ptrs.A2l[y];
    float* Cout = ptrs.C[y];
    __nv_bfloat16* Ch = ptrs.Ch[y];
    __nv_bfloat16* Cl = ptrs.Cl[y];

    int tid = threadIdx.x, wid = tid >> 5, lane = tid & 31;
    int wm = (wid >> 1) * 32;
    int wn = (wid & 1) * (BN / 2);
    int m0 = blockIdx.x * 128;

    float acc[2][NT][4];
#pragma unroll
    for (int i = 0; i < 2; i++)
#pragma unroll
        for (int j = 0; j < NT; j++)
#pragma unroll
            for (int q = 0; q < 4; q++) acc[i][j][q] = 0.f;

    int aRow = lane & 15;
    int aColSel = (lane >> 4) * 8;
    int bRow = (lane & 7) + ((lane >> 4) << 3);
    int bColSel = ((lane >> 3) & 1) * 8;

    for (int kc = 0; kc < KT / BK; kc++) {
        int k0 = kc * BK;
        const __nv_bfloat16 *Ah, *Al;
        int kA;
        if (KT == 256) {
            if (k0 < 128) { Ah = A1h; Al = A1l; kA = k0; }
            else          { Ah = A2h; Al = A2l; kA = k0 - 128; }
        } else { Ah = A1h; Al = A1l; kA = k0; }

        // --- A chunk: 128 rows x 32 bf16 (pre-split), copy 16 bf16 per thread ---
        {
            int r = tid >> 1, h = (tid & 1) * 16;
            int m = m0 + r;
            uint4 vh0, vh1, vl0, vl1;
            if (m < M) {
                const __nv_bfloat16* sh = Ah + (size_t)m * CD + kA + h;
                const __nv_bfloat16* sl = Al + (size_t)m * CD + kA + h;
                vh0 = *(const uint4*)(sh);
                vh1 = *(const uint4*)(sh + 8);
                vl0 = *(const uint4*)(sl);
                vl1 = *(const uint4*)(sl + 8);
            } else {
                vh0 = make_uint4(0, 0, 0, 0);
                vh1 = vh0; vl0 = vh0; vl1 = vh0;
            }
            uint32_t off = (uint32_t)(r * PITCH + h);
            *(uint4*)(sAh + off)     = vh0;
            *(uint4*)(sAh + off + 8) = vh1;
            *(uint4*)(sAl + off)     = vl0;
            *(uint4*)(sAl + off + 8) = vl1;
        }
        // --- B chunk: BN rows x 32 bf16, copy 16 bf16 per thread ---
        if (tid < BN * 2) {
            int n = tid >> 1, h = (tid & 1) * 16;
            const __nv_bfloat16* gh = Bhg + (size_t)n * KT + k0 + h;
            const __nv_bfloat16* gl = Blg + (size_t)n * KT + k0 + h;
            uint4 vh0 = *(const uint4*)(gh);
            uint4 vh1 = *(const uint4*)(gh + 8);
            uint4 vl0 = *(const uint4*)(gl);
            uint4 vl1 = *(const uint4*)(gl + 8);
            uint32_t off = (uint32_t)(n * PITCH + h);
            *(uint4*)(sBh + off)     = vh0;
            *(uint4*)(sBh + off + 8) = vh1;
            *(uint4*)(sBl + off)     = vl0;
            *(uint4*)(sBl + off + 8) = vl1;
        }
        __syncthreads();

#pragma unroll
        for (int kk = 0; kk < 2; kk++) {
            int kb = kk * 16;
            uint32_t ah[2][4], al[2][4];
#pragma unroll
            for (int mt = 0; mt < 2; mt++) {
                uint32_t offA = (uint32_t)((wm + mt * 16 + aRow) * PITCH + kb + aColSel) * 2;
                ldm_x4(ah[mt], smem_u32(sAh) + offA);
                ldm_x4(al[mt], smem_u32(sAl) + offA);
            }
#pragma unroll
            for (int nt2 = 0; nt2 < NT / 2; nt2++) {
                int nb = wn + nt2 * 16;
                uint32_t offB = (uint32_t)((nb + bRow) * PITCH + kb + bColSel) * 2;
                uint32_t bh[4], bl[4];
                ldm_x4(bh, smem_u32(sBh) + offB);
                ldm_x4(bl, smem_u32(sBl) + offB);
#pragma unroll
                for (int half = 0; half < 2; half++) {
                    uint32_t bhp[2] = {bh[half * 2], bh[half * 2 + 1]};
                    uint32_t blp[2] = {bl[half * 2], bl[half * 2 + 1]};
                    int nt = nt2 * 2 + half;
#pragma unroll
                    for (int mt = 0; mt < 2; mt++) {
                        mma_bf16(acc[mt][nt], ah[mt], bhp);
                        mma_bf16(acc[mt][nt], ah[mt], blp);
                        mma_bf16(acc[mt][nt], al[mt], bhp);
                    }
                }
            }
        }
        __syncthreads();
    }

    if (MODE == 3) {
        // attention epilogue: w[m] = sum_col tanh(acc + bias[col]) * W2[col]
        float wpart[2][2] = {{0.f, 0.f}, {0.f, 0.f}};
#pragma unroll
        for (int mt = 0; mt < 2; mt++) {
#pragma unroll
            for (int nt = 0; nt < NT; nt++) {
                int col = wn + nt * 8 + (lane & 3) * 2;
                float b0 = __ldg(&bias[col]), b1 = __ldg(&bias[col + 1]);
                float q0 = __ldg(&W2[col]), q1 = __ldg(&W2[col + 1]);
#pragma unroll
                for (int rh = 0; rh < 2; rh++) {
                    float v0 = acc[mt][nt][rh * 2 + 0] + b0;
                    float v1 = acc[mt][nt][rh * 2 + 1] + b1;
                    asm("tanh.approx.f32 %0, %0;" : "+f"(v0));
                    asm("tanh.approx.f32 %0, %0;" : "+f"(v1));
                    wpart[mt][rh] += v0 * q0 + v1 * q1;
                }
            }
        }
#pragma unroll
        for (int mt = 0; mt < 2; mt++)
#pragma unroll
            for (int rh = 0; rh < 2; rh++) {
                wpart[mt][rh] += __shfl_xor_sync(0xffffffffu, wpart[mt][rh], 1);
                wpart[mt][rh] += __shfl_xor_sync(0xffffffffu, wpart[mt][rh], 2);
            }
        if ((lane & 3) == 0) {
#pragma unroll
            for (int mt = 0; mt < 2; mt++)
#pragma unroll
                for (int rh = 0; rh < 2; rh++) {
                    int rloc = wm + mt * 16 + rh * 8 + (lane >> 2);
                    s_r0[wid & 1][rloc] = wpart[mt][rh];
                }
        }
        __syncthreads();
        if (tid < 128) {
            int m = m0 + tid;
            if (m < M) wout[(size_t)m * 4 + y] = s_r0[0][tid] + s_r0[1][tid];
        }
    } else {
        float lsq[2][2] = {{0.f, 0.f}, {0.f, 0.f}};
        float lsm[2][2] = {{0.f, 0.f}, {0.f, 0.f}};
#pragma unroll
        for (int mt = 0; mt < 2; mt++) {
#pragma unroll
            for (int nt = 0; nt < NT; nt++) {
                int col = wn + nt * 8 + (lane & 3) * 2;
                float b0 = __ldg(&bias[col]), b1 = __ldg(&bias[col + 1]);
#pragma unroll
                for (int rh = 0; rh < 2; rh++) {
                    int m = m0 + wm + mt * 16 + (lane >> 2) + rh * 8;
                    float v0 = acc[mt][nt][rh * 2 + 0] + b0;
                    float v1 = acc[mt][nt][rh * 2 + 1] + b1;
                    if (MODE == 1) {
                        v0 = fmaxf(v0, 0.f); v1 = fmaxf(v1, 0.f);
                        lsq[mt][rh] += v0 * v0 + v1 * v1;
                        lsm[mt][rh] += v0 + v1;
                    }
                    if (m < M) {
                        if (MODE == 1)
                            *(float2*)(Cout + (size_t)m * BN + col) = make_float2(v0, v1);
                        uint32_t hw, lw;
                        split2(v0, v1, hw, lw);
                        *(uint32_t*)(Ch + (size_t)m * BN + col) = hw;
                        *(uint32_t*)(Cl + (size_t)m * BN + col) = lw;
                    }
                }
            }
        }
        if (MODE == 1) {
#pragma unroll
            for (int mt = 0; mt < 2; mt++)
#pragma unroll
                for (int rh = 0; rh < 2; rh++) {
                    lsq[mt][rh] += __shfl_xor_sync(0xffffffffu, lsq[mt][rh], 1);
                    lsq[mt][rh] += __shfl_xor_sync(0xffffffffu, lsq[mt][rh], 2);
                    lsm[mt][rh] += __shfl_xor_sync(0xffffffffu, lsm[mt][rh], 1);
                    lsm[mt][rh] += __shfl_xor_sync(0xffffffffu, lsm[mt][rh], 2);
                }
            if ((lane & 3) == 0) {
#pragma unroll
                for (int mt = 0; mt < 2; mt++)
#pragma unroll
                    for (int rh = 0; rh < 2; rh++) {
                        int rloc = wm + mt * 16 + rh * 8 + (lane >> 2);
                        s_r0[wid & 1][rloc] = lsq[mt][rh];
                        s_r1[wid & 1][rloc] = lsm[mt][rh];
                    }
            }
            __syncthreads();
            if (tid < 128) {
                int m = m0 + tid;
                if (m < M) {
                    float sq = s_r0[0][tid] + s_r0[1][tid];
                    if (y == 0) {
                        g_n3sq[m] = sq;
                    } else {
                        g_n4sq[m] = sq;
                        g_s4[m] = s_r1[0][tid] + s_r1[1][tid];
                    }
                }
            }
        }
    }
}

// ---------------- attention pooling (warp per node) -------------------------------
__global__ void k_pool(const float* __restrict__ x3, const float* __restrict__ x4,
                       float* __restrict__ emb) {
    int node = blockIdx.x * 8 + (threadIdx.x >> 5);
    if (node >= NN) return;
    int lane = threadIdx.x & 31;
    float4 wv = ((const float4*)g_w)[node];
    float m = fmaxf(fmaxf(wv.x, wv.y), fmaxf(wv.z, wv.w));
    float e0 = __expf(wv.x - m), e1 = __expf(wv.y - m);
    float e2 = __expf(wv.z - m), e3 = __expf(wv.w - m);
    float inv = 1.f / (e0 + e1 + e2 + e3);
    float b0 = e0 * inv, b1 = e1 * inv, b2 = e2 * inv, b3 = e3 * inv;
    size_t off = (size_t)node * CD + lane * 4;
    uint2 h1 = *(const uint2*)(g_x1h + off);
    uint2 l1 = *(const uint2*)(g_x1l + off);
    uint2 h2 = *(const uint2*)(g_x2h + off);
    uint2 l2 = *(const uint2*)(g_x2l + off);
    float4 v3 = ((const float4*)x3)[(size_t)node * 32 + lane];
    float4 v4 = ((const float4*)x4)[(size_t)node * 32 + lane];
    float4 r;
    float x1v, x2v;
    x1v = __bfloat162float(__ushort_as_bfloat16((uint16_t)h1.x)) +
          __bfloat162float(__ushort_as_bfloat16((uint16_t)l1.x));
    x2v = __bfloat162float(__ushort_as_bfloat16((uint16_t)h2.x)) +
          __bfloat162float(__ushort_as_bfloat16((uint16_t)l2.x));
    r.x = b0 * x1v + b1 * x2v + b2 * v3.x + b3 * v4.x;
    x1v = __bfloat162float(__ushort_as_bfloat16((uint16_t)(h1.x >> 16))) +
          __bfloat162float(__ushort_as_bfloat16((uint16_t)(l1.x >> 16)));
    x2v = __bfloat162float(__ushort_as_bfloat16((uint16_t)(h2.x >> 16))) +
          __bfloat162float(__ushort_as_bfloat16((uint16_t)(l2.x >> 16)));
    r.y = b0 * x1v + b1 * x2v + b2 * v3.y + b3 * v4.y;
    x1v = __bfloat162float(__ushort_as_bfloat16((uint16_t)h1.y)) +
          __bfloat162float(__ushort_as_bfloat16((uint16_t)l1.y));
    x2v = __bfloat162float(__ushort_as_bfloat16((uint16_t)h2.y)) +
          __bfloat162float(__ushort_as_bfloat16((uint16_t)l2.y));
    r.z = b0 * x1v + b1 * x2v + b2 * v3.z + b3 * v4.z;
    x1v = __bfloat162float(__ushort_as_bfloat16((uint16_t)(h1.y >> 16))) +
          __bfloat162float(__ushort_as_bfloat16((uint16_t)(l1.y >> 16)));
    x2v = __bfloat162float(__ushort_as_bfloat16((uint16_t)(h2.y >> 16))) +
          __bfloat162float(__ushort_as_bfloat16((uint16_t)(l2.y >> 16)));
    r.w = b0 * x1v + b1 * x2v + b2 * v3.w + b3 * v4.w;
    ((float4*)emb)[(size_t)node * 32 + lane] = r;
}

// ---------------- host ------------------------------------------------------------
extern "C" void kernel_launch(void* const* d_in, const int* in_sizes, int n_in,
                              void* d_out, int out_size) {
    const float* x     = (const float*)d_in[0];
    const int*   row   = (const int*)d_in[1];
    const int*   col   = (const int*)d_in[2];
    const float* Wl0   = (const float*)d_in[3];
    const float* bl0   = (const float*)d_in[4];
    const float* Wr0   = (const float*)d_in[5];
    const float* Wl1   = (const float*)d_in[6];
    const float* bl1   = (const float*)d_in[7];
    const float* Wr1   = (const float*)d_in[8];
    const float* attW1 = (const float*)d_in[9];
    const float* attb1 = (const float*)d_in[10];
    const float* attW2 = (const float*)d_in[11];

    float* out = (float*)d_out;
    float* emb = out;
    float* x3  = out + (size_t)NN * CD;
    float* x4  = out + (size_t)2 * NN * CD;

    float* wbuf;
    __nv_bfloat16 *xh, *xl, *agch, *agcl, *ageh, *agel;
    __nv_bfloat16 *x3h, *x3l, *x4h, *x4l, *x1h, *x1l, *x2h, *x2l;
    __nv_bfloat16 *w0h, *w0l, *w1h, *w1l, *wah, *wal;
    cudaGetSymbolAddress((void**)&wbuf, g_w);
    cudaGetSymbolAddress((void**)&xh, g_xh);
    cudaGetSymbolAddress((void**)&xl, g_xl);
    cudaGetSymbolAddress((void**)&agch, g_agch);
    cudaGetSymbolAddress((void**)&agcl, g_agcl);
    cudaGetSymbolAddress((void**)&ageh, g_ageh);
    cudaGetSymbolAddress((void**)&agel, g_agel);
    cudaGetSymbolAddress((void**)&x3h, g_x3h);
    cudaGetSymbolAddress((void**)&x3l, g_x3l);
    cudaGetSymbolAddress((void**)&x4h, g_x4h);
    cudaGetSymbolAddress((void**)&x4l, g_x4l);
    cudaGetSymbolAddress((void**)&x1h, g_x1h);
    cudaGetSymbolAddress((void**)&x1l, g_x1l);
    cudaGetSymbolAddress((void**)&x2h, g_x2h);
    cudaGetSymbolAddress((void**)&x2l, g_x2l);
    cudaGetSymbolAddress((void**)&w0h, g_w0h);
    cudaGetSymbolAddress((void**)&w0l, g_w0l);
    cudaGetSymbolAddress((void**)&w1h, g_w1h);
    cudaGetSymbolAddress((void**)&w1l, g_w1l);
    cudaGetSymbolAddress((void**)&wah, g_wah);
    cudaGetSymbolAddress((void**)&wal, g_wal);

    const int nodeBlocks = (NN + 7) / 8;
    const int edgeBlocks = (NE + 255) / 256;
    const int TG = (NN + 127) / 128;

    // launch order: k_agg1 is the 6th launch -> profiled by ncu (-s 5 -c 1)
    k_stats1<<<nodeBlocks, 256>>>(x);                         // 1 (also zeroes degcur)
    k_deg<<<edgeBlocks, 256>>>(row);                          // 2
    k_scan<<<1, 1024>>>();                                    // 3
    k_scatter<<<edgeBlocks, 256>>>(row, col);                 // 4
    k_prep_all<<<288, 256>>>(Wl0, Wr0, Wl1, Wr1, attW1);      // 5
    k_agg1<<<nodeBlocks, 256>>>(x);                           // 6  <- profiled

    // layer 1: x3 = relu([aggc|x]@W0+bl0), x4 = relu([agge|x]@W0+bl0); + split + stats
    {
        GemmPtrs p = {};
        p.A1h[0] = agch; p.A1l[0] = agcl; p.A2h[0] = xh; p.A2l[0] = xl;
        p.C[0] = x3; p.Ch[0] = x3h; p.Cl[0] = x3l;
        p.A1h[1] = ageh; p.A1l[1] = agel; p.A2h[1] = xh; p.A2l[1] = xl;
        p.C[1] = x4; p.Ch[1] = x4h; p.Cl[1] = x4l;
        k_mma_gemm<128, 256, 1><<<dim3(TG, 2), 256>>>(p, w0h, w0l, bl0, nullptr, nullptr, NN);
    }

    k_agg2<<<nodeBlocks, 256>>>(x3, x4);

    // layer 2: x1/x2 (split only)
    {
        GemmPtrs p = {};
        p.A1h[0] = agch; p.A1l[0] = agcl; p.A2h[0] = x3h; p.A2l[0] = x3l;
        p.Ch[0] = x1h; p.Cl[0] = x1l;
        p.A1h[1] = ageh; p.A1l[1] = agel; p.A2h[1] = x4h; p.A2l[1] = x4l;
        p.Ch[1] = x2h; p.Cl[1] = x2l;
        k_mma_gemm<128, 256, 0><<<dim3(TG, 2), 256>>>(p, w1h, w1l, bl1, nullptr, nullptr, NN);
    }

    // attention logits (4 branches)
    {
        GemmPtrs p = {};
        p.A1h[0] = x1h; p.A1l[0] = x1l;
        p.A1h[1] = x2h; p.A1l[1] = x2l;
        p.A1h[2] = x3h; p.A1l[2] = x3l;
        p.A1h[3] = x4h; p.A1l[3] = x4l;
        k_mma_gemm<64, 128, 3><<<dim3(TG, 4), 256>>>(p, wah, wal, attb1, attW2, wbuf, NN);
    }

    k_pool<<<nodeBlocks, 256>>>(x3, x4, emb);
}

// round 11
// speedup vs baseline: 1.0938x; 1.0938x over previous
#include <cuda_runtime.h>
#include <cuda_bf16.h>
#include <math.h>
#include <stdint.h>

#define NN 50000
#define NE 800000
#define CD 128
#define AH 64

// ---------------- scratch (static device globals) ---------------------------------
__device__ float g_nsq[NN];
__device__ float g_ns[NN];
__device__ float g_n3sq[NN];
__device__ float g_n4sq[NN];
__device__ float g_s4[NN];
__device__ int   g_degcur[2 * NN];   // [0..NN) deg, [NN..2NN) cursor
__device__ int   g_rowptr[NN + 1];
__device__ int   g_csr[NE];
__device__ float g_aggc[(size_t)NN * CD];
__device__ float g_agge[(size_t)NN * CD];
__device__ float g_x1[(size_t)NN * CD];
__device__ float g_x2[(size_t)NN * CD];
__device__ float g_w[(size_t)NN * 4];    // attention logits [node][branch]
// split-bf16 transposed weights: [N rows x K cols]
__device__ __nv_bfloat16 g_w0h[128 * 256];
__device__ __nv_bfloat16 g_w0l[128 * 256];
__device__ __nv_bfloat16 g_w1h[128 * 256];
__device__ __nv_bfloat16 g_w1l[128 * 256];
__device__ __nv_bfloat16 g_wah[64 * 128];
__device__ __nv_bfloat16 g_wal[64 * 128];

struct GemmPtrs {
    const float* A1[4];
    const float* A2[4];
    float*       C[4];
};

__device__ __forceinline__ uint32_t smem_u32(const void* p) {
    uint32_t a;
    asm("{ .reg .u64 t; cvta.to.shared.u64 t, %1; cvt.u32.u64 %0, t; }" : "=r"(a) : "l"(p));
    return a;
}

__device__ __forceinline__ float wredsum(float v) {
#pragma unroll
    for (int o = 16; o; o >>= 1) v += __shfl_xor_sync(0xffffffffu, v, o);
    return v;
}

// ---------------- per-node stats of x + zero degcur --------------------------------
__global__ void k_stats1(const float* __restrict__ x) {
    int gid = blockIdx.x * 256 + threadIdx.x;
    if (gid < 2 * NN) g_degcur[gid] = 0;
    int node = blockIdx.x * 8 + (threadIdx.x >> 5);
    if (node >= NN) return;
    int lane = threadIdx.x & 31;
    float4 v = *(const float4*)(x + (size_t)node * CD + lane * 4);
    float sq = v.x * v.x + v.y * v.y + v.z * v.z + v.w * v.w;
    float s  = v.x + v.y + v.z + v.w;
    sq = wredsum(sq);
    s  = wredsum(s);
    if (lane == 0) { g_nsq[node] = sq; g_ns[node] = s; }
}

// ---------------- CSR build -------------------------------------------------------
__global__ void k_deg(const int* __restrict__ row) {
    int e = blockIdx.x * blockDim.x + threadIdx.x;
    if (e < NE) atomicAdd(&g_degcur[row[e]], 1);
}

__global__ void k_scan() {
    const int PER = (NN + 1023) / 1024;
    int tid = threadIdx.x;
    int t0 = tid * PER;
    int sum = 0;
    for (int i = 0; i < PER; i++) {
        int idx = t0 + i;
        if (idx < NN) sum += g_degcur[idx];
    }
    int lane = tid & 31, wid = tid >> 5;
    int v = sum;
#pragma unroll
    for (int o = 1; o < 32; o <<= 1) {
        int t = __shfl_up_sync(0xffffffffu, v, o);
        if (lane >= o) v += t;
    }
    __shared__ int wsum[32];
    if (lane == 31) wsum[wid] = v;
    __syncthreads();
    if (wid == 0) {
        int w = wsum[lane];
#pragma unroll
        for (int o = 1; o < 32; o <<= 1) {
            int t = __shfl_up_sync(0xffffffffu, w, o);
            if (lane >= o) w += t;
        }
        wsum[lane] = w;
    }
    __syncthreads();
    int offset = v - sum + (wid ? wsum[wid - 1] : 0);
    int run = offset;
    for (int i = 0; i < PER; i++) {
        int idx = t0 + i;
        if (idx < NN) { g_rowptr[idx] = run; run += g_degcur[idx]; }
    }
    if (t0 < NN && t0 + PER >= NN) g_rowptr[NN] = run;
}

__global__ void k_scatter(const int* __restrict__ row, const int* __restrict__ col) {
    int e = blockIdx.x * blockDim.x + threadIdx.x;
    if (e >= NE) return;
    int r = row[e];
    int p = atomicAdd(&g_degcur[NN + r], 1);
    g_csr[g_rowptr[r] + p] = col[e];
}

// ---------------- fused weight prep: transpose + bf16 split ------------------------
__global__ void k_prep_all(const float* __restrict__ Wl0, const float* __restrict__ Wr0,
                           const float* __restrict__ Wl1, const float* __restrict__ Wr1,
                           const float* __restrict__ attW1) {
    int i = blockIdx.x * blockDim.x + threadIdx.x;
    float v;
    __nv_bfloat16 *oh, *ol;
    int idx;
    if (i < 32768) {
        int n = i / 256, k = i % 256;
        v = (k < 128) ? Wl0[(size_t)k * 128 + n] : Wr0[(size_t)(k - 128) * 128 + n];
        oh = g_w0h; ol = g_w0l; idx = i;
    } else if (i < 65536) {
        int j = i - 32768;
        int n = j / 256, k = j % 256;
        v = (k < 128) ? Wl1[(size_t)k * 128 + n] : Wr1[(size_t)(k - 128) * 128 + n];
        oh = g_w1h; ol = g_w1l; idx = j;
    } else if (i < 73728) {
        int j = i - 65536;
        int n = j / 128, k = j % 128;
        v = attW1[(size_t)k * 64 + n];
        oh = g_wah; ol = g_wal; idx = j;
    } else return;
    __nv_bfloat16 h = __float2bfloat16(v);
    oh[idx] = h;
    ol[idx] = __float2bfloat16(v - __bfloat162float(h));
}

// ---------------- fused layer-1 agg: warp/node, half-warp/edge, unroll 2 -----------
__global__ void k_agg1(const float* __restrict__ x) {
    int node = blockIdx.x * 8 + (threadIdx.x >> 5);
    if (node >= NN) return;
    int lane = threadIdx.x & 31;
    int half = lane >> 4, sub = lane & 15;
    const float4* xb = (const float4*)x;
    float4 xi0 = xb[(size_t)node * 32 + sub * 2];
    float4 xi1 = xb[(size_t)node * 32 + sub * 2 + 1];
    float nsq_i = g_nsq[node], ns_i = g_ns[node];
    int s = g_rowptr[node], t = g_rowptr[node + 1];
    float ac[8] = {0.f, 0.f, 0.f, 0.f, 0.f, 0.f, 0.f, 0.f};
    float ae[8] = {0.f, 0.f, 0.f, 0.f, 0.f, 0.f, 0.f, 0.f};
    for (int base = s; base < t; base += 4) {
        int jA = base + half, jB = base + 2 + half;
        bool okA = jA < t, okB = jB < t;
        int cA = okA ? __ldg(&g_csr[jA]) : node;
        int cB = okB ? __ldg(&g_csr[jB]) : node;
        float4 vA0 = xb[(size_t)cA * 32 + sub * 2];
        float4 vA1 = xb[(size_t)cA * 32 + sub * 2 + 1];
        float4 vB0 = xb[(size_t)cB * 32 + sub * 2];
        float4 vB1 = xb[(size_t)cB * 32 + sub * 2 + 1];
        float dA = xi0.x * vA0.x + xi0.y * vA0.y + xi0.z * vA0.z + xi0.w * vA0.w
                 + xi1.x * vA1.x + xi1.y * vA1.y + xi1.z * vA1.z + xi1.w * vA1.w;
        float dB = xi0.x * vB0.x + xi0.y * vB0.y + xi0.z * vB0.z + xi0.w * vB0.w
                 + xi1.x * vB1.x + xi1.y * vB1.y + xi1.z * vB1.z + xi1.w * vB1.w;
#pragma unroll
        for (int o = 8; o; o >>= 1) {
            dA += __shfl_xor_sync(0xffffffffu, dA, o);
            dB += __shfl_xor_sync(0xffffffffu, dB, o);
        }
        float nsqA = g_nsq[cA], nsA = g_ns[cA];
        float nsqB = g_nsq[cB], nsB = g_ns[cB];
        float wcA = dA / fmaxf(sqrtf(nsq_i * nsqA), 1e-8f);
        float qA = nsq_i + nsqA - 2.f * dA + 2e-6f * (ns_i - nsA) + 1.28e-10f;
        float weA = sqrtf(fmaxf(qA, 0.f));
        float wcB = dB / fmaxf(sqrtf(nsq_i * nsqB), 1e-8f);
        float qB = nsq_i + nsqB - 2.f * dB + 2e-6f * (ns_i - nsB) + 1.28e-10f;
        float weB = sqrtf(fmaxf(qB, 0.f));
        if (!okA) { wcA = 0.f; weA = 0.f; }
        if (!okB) { wcB = 0.f; weB = 0.f; }
        ac[0] += wcA * vA0.x + wcB * vB0.x; ac[1] += wcA * vA0.y + wcB * vB0.y;
        ac[2] += wcA * vA0.z + wcB * vB0.z; ac[3] += wcA * vA0.w + wcB * vB0.w;
        ac[4] += wcA * vA1.x + wcB * vB1.x; ac[5] += wcA * vA1.y + wcB * vB1.y;
        ac[6] += wcA * vA1.z + wcB * vB1.z; ac[7] += wcA * vA1.w + wcB * vB1.w;
        ae[0] += weA * vA0.x + weB * vB0.x; ae[1] += weA * vA0.y + weB * vB0.y;
        ae[2] += weA * vA0.z + weB * vB0.z; ae[3] += weA * vA0.w + weB * vB0.w;
        ae[4] += weA * vA1.x + weB * vB1.x; ae[5] += weA * vA1.y + weB * vB1.y;
        ae[6] += weA * vA1.z + weB * vB1.z; ae[7] += weA * vA1.w + weB * vB1.w;
    }
#pragma unroll
    for (int i = 0; i < 8; i++) {
        ac[i] += __shfl_xor_sync(0xffffffffu, ac[i], 16);
        ae[i] += __shfl_xor_sync(0xffffffffu, ae[i], 16);
    }
    float inv = 1.f / (float)max(t - s, 1);
    int fidx = node * 32 + sub * 2 + half;
    int b = half * 4;
    ((float4*)g_aggc)[fidx] =
        make_float4(ac[b] * inv, ac[b + 1] * inv, ac[b + 2] * inv, ac[b + 3] * inv);
    ((float4*)g_agge)[fidx] =
        make_float4(ae[b] * inv, ae[b + 1] * inv, ae[b + 2] * inv, ae[b + 3] * inv);
}

// ---------------- fused layer-2 agg: warp per node, half-warp per edge -------------
__global__ void k_agg2(const float* __restrict__ x3, const float* __restrict__ x4) {
    int node = blockIdx.x * 8 + (threadIdx.x >> 5);
    if (node >= NN) return;
    int lane = threadIdx.x & 31;
    int half = lane >> 4, sub = lane & 15;
    const float4* x3b = (const float4*)x3;
    const float4* x4b = (const float4*)x4;
    float4 a30 = x3b[(size_t)node * 32 + sub * 2];
    float4 a31 = x3b[(size_t)node * 32 + sub * 2 + 1];
    float4 a40 = x4b[(size_t)node * 32 + sub * 2];
    float4 a41 = x4b[(size_t)node * 32 + sub * 2 + 1];
    float n3i = g_n3sq[node], n4i = g_n4sq[node], s4i = g_s4[node];
    int s = g_rowptr[node], t = g_rowptr[node + 1];
    float ac[8] = {0.f, 0.f, 0.f, 0.f, 0.f, 0.f, 0.f, 0.f};
    float ae[8] = {0.f, 0.f, 0.f, 0.f, 0.f, 0.f, 0.f, 0.f};
    for (int base = s; base < t; base += 2) {
        int j = base + half;
        bool ok = j < t;
        int c = ok ? __ldg(&g_csr[j]) : node;
        float4 v30 = x3b[(size_t)c * 32 + sub * 2];
        float4 v31 = x3b[(size_t)c * 32 + sub * 2 + 1];
        float4 v40 = x4b[(size_t)c * 32 + sub * 2];
        float4 v41 = x4b[(size_t)c * 32 + sub * 2 + 1];
        float d3 = a30.x * v30.x + a30.y * v30.y + a30.z * v30.z + a30.w * v30.w
                 + a31.x * v31.x + a31.y * v31.y + a31.z * v31.z + a31.w * v31.w;
        float d4 = a40.x * v40.x + a40.y * v40.y + a40.z * v40.z + a40.w * v40.w
                 + a41.x * v41.x + a41.y * v41.y + a41.z * v41.z + a41.w * v41.w;
#pragma unroll
        for (int o = 8; o; o >>= 1) {
            d3 += __shfl_xor_sync(0xffffffffu, d3, o);
            d4 += __shfl_xor_sync(0xffffffffu, d4, o);
        }
        float wc = d3 / fmaxf(sqrtf(n3i * g_n3sq[c]), 1e-8f);
        float q = n4i + g_n4sq[c] - 2.f * d4 + 2e-6f * (s4i - g_s4[c]) + 1.28e-10f;
        float we = sqrtf(fmaxf(q, 0.f));
        if (!ok) { wc = 0.f; we = 0.f; }
        ac[0] += wc * v30.x; ac[1] += wc * v30.y; ac[2] += wc * v30.z; ac[3] += wc * v30.w;
        ac[4] += wc * v31.x; ac[5] += wc * v31.y; ac[6] += wc * v31.z; ac[7] += wc * v31.w;
        ae[0] += we * v40.x; ae[1] += we * v40.y; ae[2] += we * v40.z; ae[3] += we * v40.w;
        ae[4] += we * v41.x; ae[5] += we * v41.y; ae[6] += we * v41.z; ae[7] += we * v41.w;
    }
#pragma unroll
    for (int i = 0; i < 8; i++) {
        ac[i] += __shfl_xor_sync(0xffffffffu, ac[i], 16);
        ae[i] += __shfl_xor_sync(0xffffffffu, ae[i], 16);
    }
    float inv = 1.f / (float)max(t - s, 1);
    int fidx = node * 32 + sub * 2 + half;
    int b = half * 4;
    ((float4*)g_aggc)[fidx] =
        make_float4(ac[b] * inv, ac[b + 1] * inv, ac[b + 2] * inv, ac[b + 3] * inv);
    ((float4*)g_agge)[fidx] =
        make_float4(ae[b] * inv, ae[b + 1] * inv, ae[b + 2] * inv, ae[b + 3] * inv);
}

// ---------------- mma helpers ------------------------------------------------------
__device__ __forceinline__ void ldm_x4(uint32_t* r, uint32_t addr) {
    asm volatile("ldmatrix.sync.aligned.m8n8.x4.shared.b16 {%0,%1,%2,%3}, [%4];"
                 : "=r"(r[0]), "=r"(r[1]), "=r"(r[2]), "=r"(r[3]) : "r"(addr));
}
__device__ __forceinline__ void mma_bf16(float* c, const uint32_t* a, const uint32_t* b) {
    asm volatile(
        "mma.sync.aligned.m16n8k16.row.col.f32.bf16.bf16.f32 "
        "{%0,%1,%2,%3}, {%4,%5,%6,%7}, {%8,%9}, {%0,%1,%2,%3};"
        : "+f"(c[0]), "+f"(c[1]), "+f"(c[2]), "+f"(c[3])
        : "r"(a[0]), "r"(a[1]), "r"(a[2]), "r"(a[3]), "r"(b[0]), "r"(b[1]));
}
__device__ __forceinline__ uint32_t pack_bf16(float a, float b) {
    __nv_bfloat16 h0 = __float2bfloat16(a);
    __nv_bfloat16 h1 = __float2bfloat16(b);
    return (uint32_t)__bfloat16_as_ushort(h0) | ((uint32_t)__bfloat16_as_ushort(h1) << 16);
}

// ---------------- split-bf16 tensor-core GEMM (batched via blockIdx.y) -------------
// MODE: 0 = layer2 plain, 1 = layer1 (relu + fused x3/x4 row stats), 3 = attention
template <int BN, int KT, int MODE>
__global__ __launch_bounds__(256, 2) void k_mma_gemm(
    GemmPtrs ptrs,
    const __nv_bfloat16* __restrict__ Bhg, const __nv_bfloat16* __restrict__ Blg,
    const float* __restrict__ bias, const float* __restrict__ W2,
    float* __restrict__ wout, int M) {
    constexpr int BK = 32;
    constexpr int PITCH = 40;
    constexpr int NT = BN / 16;

    __shared__ __nv_bfloat16 sAh[128 * PITCH];
    __shared__ __nv_bfloat16 sAl[128 * PITCH];
    __shared__ __nv_bfloat16 sBh[BN * PITCH];
    __shared__ __nv_bfloat16 sBl[BN * PITCH];
    __shared__ float s_r0[2][128];
    __shared__ float s_r1[2][128];

    const float* A1 = ptrs.A1[blockIdx.y];
    const float* A2 = ptrs.A2[blockIdx.y];
    float* Cout = ptrs.C[blockIdx.y];

    int tid = threadIdx.x, wid = tid >> 5, lane = tid & 31;
    int wm = (wid >> 1) * 32;
    int wn = (wid & 1) * (BN / 2);
    int m0 = blockIdx.x * 128;

    float acc[2][NT][4];
#pragma unroll
    for (int i = 0; i < 2; i++)
#pragma unroll
        for (int j = 0; j < NT; j++)
#pragma unroll
            for (int q = 0; q < 4; q++) acc[i][j][q] = 0.f;

    int aRow = lane & 15;
    int aColSel = (lane >> 4) * 8;
    int bRow = (lane & 7) + ((lane >> 4) << 3);
    int bColSel = ((lane >> 3) & 1) * 8;

    for (int kc = 0; kc < KT / BK; kc++) {
        int k0 = kc * BK;
        const float* As;
        int kA;
        if (KT == 256) { As = (k0 < 128) ? A1 : A2; kA = k0 & 127; }
        else           { As = A1; kA = k0; }

        {
            int r = tid >> 1, h = (tid & 1) * 16;
            int m = m0 + r;
            float4 f0, f1, f2, f3;
            if (m < M) {
                const float* s = As + (size_t)m * CD + kA + h;
                f0 = *(const float4*)(s);
                f1 = *(const float4*)(s + 4);
                f2 = *(const float4*)(s + 8);
                f3 = *(const float4*)(s + 12);
            } else {
                f0 = make_float4(0.f, 0.f, 0.f, 0.f);
                f1 = f0; f2 = f0; f3 = f0;
            }
            float fv[16] = {f0.x, f0.y, f0.z, f0.w, f1.x, f1.y, f1.z, f1.w,
                            f2.x, f2.y, f2.z, f2.w, f3.x, f3.y, f3.z, f3.w};
            uint32_t hw[8], lw[8];
#pragma unroll
            for (int j = 0; j < 8; j++) {
                float a = fv[2 * j], b = fv[2 * j + 1];
                hw[j] = pack_bf16(a, b);
                float ra = a - __bfloat162float(__ushort_as_bfloat16((uint16_t)hw[j]));
                float rb = b - __bfloat162float(__ushort_as_bfloat16((uint16_t)(hw[j] >> 16)));
                lw[j] = pack_bf16(ra, rb);
            }
            uint32_t off = (uint32_t)(r * PITCH + h);
            *(uint4*)(sAh + off)     = make_uint4(hw[0], hw[1], hw[2], hw[3]);
            *(uint4*)(sAh + off + 8) = make_uint4(hw[4], hw[5], hw[6], hw[7]);
            *(uint4*)(sAl + off)     = make_uint4(lw[0], lw[1], lw[2], lw[3]);
            *(uint4*)(sAl + off + 8) = make_uint4(lw[4], lw[5], lw[6], lw[7]);
        }
        if (tid < BN * 2) {
            int n = tid >> 1, h = (tid & 1) * 16;
            const __nv_bfloat16* gh = Bhg + (size_t)n * KT + k0 + h;
            const __nv_bfloat16* gl = Blg + (size_t)n * KT + k0 + h;
            uint4 vh0 = *(const uint4*)(gh);
            uint4 vh1 = *(const uint4*)(gh + 8);
            uint4 vl0 = *(const uint4*)(gl);
            uint4 vl1 = *(const uint4*)(gl + 8);
            uint32_t off = (uint32_t)(n * PITCH + h);
            *(uint4*)(sBh + off)     = vh0;
            *(uint4*)(sBh + off + 8) = vh1;
            *(uint4*)(sBl + off)     = vl0;
            *(uint4*)(sBl + off + 8) = vl1;
        }
        __syncthreads();

#pragma unroll
        for (int kk = 0; kk < 2; kk++) {
            int kb = kk * 16;
            uint32_t ah[2][4], al[2][4];
#pragma unroll
            for (int mt = 0; mt < 2; mt++) {
                uint32_t offA = (uint32_t)((wm + mt * 16 + aRow) * PITCH + kb + aColSel) * 2;
                ldm_x4(ah[mt], smem_u32(sAh) + offA);
                ldm_x4(al[mt], smem_u32(sAl) + offA);
            }
#pragma unroll
            for (int nt2 = 0; nt2 < NT / 2; nt2++) {
                int nb = wn + nt2 * 16;
                uint32_t offB = (uint32_t)((nb + bRow) * PITCH + kb + bColSel) * 2;
                uint32_t bh[4], bl[4];
                ldm_x4(bh, smem_u32(sBh) + offB);
                ldm_x4(bl, smem_u32(sBl) + offB);
#pragma unroll
                for (int half = 0; half < 2; half++) {
                    uint32_t bhp[2] = {bh[half * 2], bh[half * 2 + 1]};
                    uint32_t blp[2] = {bl[half * 2], bl[half * 2 + 1]};
                    int nt = nt2 * 2 + half;
#pragma unroll
                    for (int mt = 0; mt < 2; mt++) {
                        mma_bf16(acc[mt][nt], ah[mt], bhp);
                        mma_bf16(acc[mt][nt], ah[mt], blp);
                        mma_bf16(acc[mt][nt], al[mt], bhp);
                    }
                }
            }
        }
        __syncthreads();
    }

    if (MODE == 3) {
        // attention epilogue: w[m] = sum_col tanh(acc + bias[col]) * W2[col]
        float wpart[2][2] = {{0.f, 0.f}, {0.f, 0.f}};
#pragma unroll
        for (int mt = 0; mt < 2; mt++) {
#pragma unroll
            for (int nt = 0; nt < NT; nt++) {
                int col = wn + nt * 8 + (lane & 3) * 2;
                float b0 = __ldg(&bias[col]), b1 = __ldg(&bias[col + 1]);
                float q0 = __ldg(&W2[col]), q1 = __ldg(&W2[col + 1]);
#pragma unroll
                for (int rh = 0; rh < 2; rh++) {
                    float v0 = acc[mt][nt][rh * 2 + 0] + b0;
                    float v1 = acc[mt][nt][rh * 2 + 1] + b1;
                    asm("tanh.approx.f32 %0, %0;" : "+f"(v0));
                    asm("tanh.approx.f32 %0, %0;" : "+f"(v1));
                    wpart[mt][rh] += v0 * q0 + v1 * q1;
                }
            }
        }
#pragma unroll
        for (int mt = 0; mt < 2; mt++)
#pragma unroll
            for (int rh = 0; rh < 2; rh++) {
                wpart[mt][rh] += __shfl_xor_sync(0xffffffffu, wpart[mt][rh], 1);
                wpart[mt][rh] += __shfl_xor_sync(0xffffffffu, wpart[mt][rh], 2);
            }
        if ((lane & 3) == 0) {
#pragma unroll
            for (int mt = 0; mt < 2; mt++)
#pragma unroll
                for (int rh = 0; rh < 2; rh++) {
                    int rloc = wm + mt * 16 + rh * 8 + (lane >> 2);
                    s_r0[wid & 1][rloc] = wpart[mt][rh];
                }
        }
        __syncthreads();
        if (tid < 128) {
            int m = m0 + tid;
            if (m < M) wout[(size_t)m * 4 + blockIdx.y] = s_r0[0][tid] + s_r0[1][tid];
        }
    } else {
        float lsq[2][2] = {{0.f, 0.f}, {0.f, 0.f}};
        float lsm[2][2] = {{0.f, 0.f}, {0.f, 0.f}};
#pragma unroll
        for (int mt = 0; mt < 2; mt++) {
#pragma unroll
            for (int nt = 0; nt < NT; nt++) {
                int col = wn + nt * 8 + (lane & 3) * 2;
                float b0 = __ldg(&bias[col]), b1 = __ldg(&bias[col + 1]);
#pragma unroll
                for (int rh = 0; rh < 2; rh++) {
                    int m = m0 + wm + mt * 16 + (lane >> 2) + rh * 8;
                    float v0 = acc[mt][nt][rh * 2 + 0] + b0;
                    float v1 = acc[mt][nt][rh * 2 + 1] + b1;
                    if (MODE == 1) {
                        v0 = fmaxf(v0, 0.f); v1 = fmaxf(v1, 0.f);
                        lsq[mt][rh] += v0 * v0 + v1 * v1;
                        lsm[mt][rh] += v0 + v1;
                    }
                    if (m < M)
                        *(float2*)(Cout + (size_t)m * BN + col) = make_float2(v0, v1);
                }
            }
        }
        if (MODE == 1) {
            // fused x3/x4 row stats (replaces k_stats2)
#pragma unroll
            for (int mt = 0; mt < 2; mt++)
#pragma unroll
                for (int rh = 0; rh < 2; rh++) {
                    lsq[mt][rh] += __shfl_xor_sync(0xffffffffu, lsq[mt][rh], 1);
                    lsq[mt][rh] += __shfl_xor_sync(0xffffffffu, lsq[mt][rh], 2);
                    lsm[mt][rh] += __shfl_xor_sync(0xffffffffu, lsm[mt][rh], 1);
                    lsm[mt][rh] += __shfl_xor_sync(0xffffffffu, lsm[mt][rh], 2);
                }
            if ((lane & 3) == 0) {
#pragma unroll
                for (int mt = 0; mt < 2; mt++)
#pragma unroll
                    for (int rh = 0; rh < 2; rh++) {
                        int rloc = wm + mt * 16 + rh * 8 + (lane >> 2);
                        s_r0[wid & 1][rloc] = lsq[mt][rh];
                        s_r1[wid & 1][rloc] = lsm[mt][rh];
                    }
            }
            __syncthreads();
            if (tid < 128) {
                int m = m0 + tid;
                if (m < M) {
                    float sq = s_r0[0][tid] + s_r0[1][tid];
                    if (blockIdx.y == 0) {
                        g_n3sq[m] = sq;
                    } else {
                        g_n4sq[m] = sq;
                        g_s4[m] = s_r1[0][tid] + s_r1[1][tid];
                    }
                }
            }
        }
    }
}

// ---------------- attention pooling (warp per node) -------------------------------
__global__ void k_pool(const float* __restrict__ x3, const float* __restrict__ x4,
                       float* __restrict__ emb) {
    int node = blockIdx.x * 8 + (threadIdx.x >> 5);
    if (node >= NN) return;
    int lane = threadIdx.x & 31;
    float4 wv = ((const float4*)g_w)[node];
    float m = fmaxf(fmaxf(wv.x, wv.y), fmaxf(wv.z, wv.w));
    float e0 = __expf(wv.x - m), e1 = __expf(wv.y - m);
    float e2 = __expf(wv.z - m), e3 = __expf(wv.w - m);
    float inv = 1.f / (e0 + e1 + e2 + e3);
    float b0 = e0 * inv, b1 = e1 * inv, b2 = e2 * inv, b3 = e3 * inv;
    float4 v1 = ((const float4*)g_x1)[(size_t)node * 32 + lane];
    float4 v2 = ((const float4*)g_x2)[(size_t)node * 32 + lane];
    float4 v3 = ((const float4*)x3)[(size_t)node * 32 + lane];
    float4 v4 = ((const float4*)x4)[(size_t)node * 32 + lane];
    float4 r;
    r.x = b0 * v1.x + b1 * v2.x + b2 * v3.x + b3 * v4.x;
    r.y = b0 * v1.y + b1 * v2.y + b2 * v3.y + b3 * v4.y;
    r.z = b0 * v1.z + b1 * v2.z + b2 * v3.z + b3 * v4.z;
    r.w = b0 * v1.w + b1 * v2.w + b2 * v3.w + b3 * v4.w;
    ((float4*)emb)[(size_t)node * 32 + lane] = r;
}

// ---------------- host ------------------------------------------------------------
extern "C" void kernel_launch(void* const* d_in, const int* in_sizes, int n_in,
                              void* d_out, int out_size) {
    const float* x     = (const float*)d_in[0];
    const int*   row   = (const int*)d_in[1];
    const int*   col   = (const int*)d_in[2];
    const float* Wl0   = (const float*)d_in[3];
    const float* bl0   = (const float*)d_in[4];
    const float* Wr0   = (const float*)d_in[5];
    const float* Wl1   = (const float*)d_in[6];
    const float* bl1   = (const float*)d_in[7];
    const float* Wr1   = (const float*)d_in[8];
    const float* attW1 = (const float*)d_in[9];
    const float* attb1 = (const float*)d_in[10];
    const float* attW2 = (const float*)d_in[11];

    float* out = (float*)d_out;
    float* emb = out;
    float* x3  = out + (size_t)NN * CD;
    float* x4  = out + (size_t)2 * NN * CD;

    float *aggc, *agge, *x1b, *x2b, *wbuf;
    __nv_bfloat16 *w0h, *w0l, *w1h, *w1l, *wah, *wal;
    cudaGetSymbolAddress((void**)&aggc, g_aggc);
    cudaGetSymbolAddress((void**)&agge, g_agge);
    cudaGetSymbolAddress((void**)&x1b, g_x1);
    cudaGetSymbolAddress((void**)&x2b, g_x2);
    cudaGetSymbolAddress((void**)&wbuf, g_w);
    cudaGetSymbolAddress((void**)&w0h, g_w0h);
    cudaGetSymbolAddress((void**)&w0l, g_w0l);
    cudaGetSymbolAddress((void**)&w1h, g_w1h);
    cudaGetSymbolAddress((void**)&w1l, g_w1l);
    cudaGetSymbolAddress((void**)&wah, g_wah);
    cudaGetSymbolAddress((void**)&wal, g_wal);

    const int nodeBlocks = (NN + 7) / 8;
    const int edgeBlocks = (NE + 255) / 256;
    const int TG = (NN + 127) / 128;

    k_stats1<<<nodeBlocks, 256>>>(x);                         // also zeroes degcur
    k_deg<<<edgeBlocks, 256>>>(row);
    k_scan<<<1, 1024>>>();
    k_scatter<<<edgeBlocks, 256>>>(row, col);
    k_prep_all<<<288, 256>>>(Wl0, Wr0, Wl1, Wr1, attW1);
    k_agg1<<<nodeBlocks, 256>>>(x);

    // layer 1 (batched): x3/x4 = relu([agg|x]@W0+bl0), with fused row stats
    {
        GemmPtrs p = {};
        p.A1[0] = aggc; p.A2[0] = x; p.C[0] = x3;
        p.A1[1] = agge; p.A2[1] = x; p.C[1] = x4;
        k_mma_gemm<128, 256, 1><<<dim3(TG, 2), 256>>>(p, w0h, w0l, bl0, nullptr, nullptr, NN);
    }

    k_agg2<<<nodeBlocks, 256>>>(x3, x4);

    // layer 2 (batched)
    {
        GemmPtrs p = {};
        p.A1[0] = aggc; p.A2[0] = x3; p.C[0] = x1b;
        p.A1[1] = agge; p.A2[1] = x4; p.C[1] = x2b;
        k_mma_gemm<128, 256, 0><<<dim3(TG, 2), 256>>>(p, w1h, w1l, bl1, nullptr, nullptr, NN);
    }

    // attention logits (batched, 4 branches)
    {
        GemmPtrs p = {};
        p.A1[0] = x1b; p.A1[1] = x2b; p.A1[2] = x3; p.A1[3] = x4;
        k_mma_gemm<64, 128, 3><<<dim3(TG, 4), 256>>>(p, wah, wal, attb1, attW2, wbuf, NN);
    }

    k_pool<<<nodeBlocks, 256>>>(x3, x4, emb);
}